// round 1
// baseline (speedup 1.0000x reference)
#include <cuda_runtime.h>
#include <math.h>
#include <float.h>

#define SQ   2048
#define HID  4096
#define NH   32
#define NKV  8
#define HD   128
#define KVD  1024   // NKV * HD

// Scratch (allocation-free rule: __device__ globals)
__device__ float g_Q[SQ * HID];                 // 32 MB  (post-RoPE, pre-scaled by 1/sqrt(hd))
__device__ float g_K[SQ * KVD];                 // 8 MB
__device__ float g_V[SQ * KVD];                 // 8 MB
__device__ float g_A[SQ * HID];                 // 32 MB  (attention out, [s, h*128+d])
__device__ float g_P[(size_t)NH * SQ * SQ];     // 512 MB (scores -> probs)

// ---------------------------------------------------------------------------
// Generic C[M,N] = A[M,K] @ W[N,K]^T   (both row-major, K-contiguous)
// 128x128 tile, BK=8, 256 threads, 8x8 microtile.
// ---------------------------------------------------------------------------
__global__ __launch_bounds__(256) void gemm_nt(const float* __restrict__ A,
                                               const float* __restrict__ W,
                                               float* __restrict__ C,
                                               int M, int N, int K) {
    __shared__ float As[8][128];
    __shared__ float Ws[8][128];
    int tid  = threadIdx.x;
    int arow = tid >> 1;              // 0..127
    int acol = (tid & 1) << 2;        // 0 or 4
    const float* Ap = A + (size_t)(blockIdx.y * 128 + arow) * K + acol;
    const float* Wp = W + (size_t)(blockIdx.x * 128 + arow) * K + acol;
    int ty = tid >> 4, tx = tid & 15;

    float acc[8][8] = {};
    for (int k0 = 0; k0 < K; k0 += 8) {
        float4 av = *(const float4*)(Ap + k0);
        float4 wv = *(const float4*)(Wp + k0);
        As[acol + 0][arow] = av.x; As[acol + 1][arow] = av.y;
        As[acol + 2][arow] = av.z; As[acol + 3][arow] = av.w;
        Ws[acol + 0][arow] = wv.x; Ws[acol + 1][arow] = wv.y;
        Ws[acol + 2][arow] = wv.z; Ws[acol + 3][arow] = wv.w;
        __syncthreads();
#pragma unroll
        for (int kk = 0; kk < 8; kk++) {
            float a[8], b[8];
            *(float4*)(a)     = *(const float4*)&As[kk][ty * 8];
            *(float4*)(a + 4) = *(const float4*)&As[kk][ty * 8 + 4];
            *(float4*)(b)     = *(const float4*)&Ws[kk][tx * 8];
            *(float4*)(b + 4) = *(const float4*)&Ws[kk][tx * 8 + 4];
#pragma unroll
            for (int i = 0; i < 8; i++)
#pragma unroll
                for (int j = 0; j < 8; j++)
                    acc[i][j] += a[i] * b[j];
        }
        __syncthreads();
    }
#pragma unroll
    for (int i = 0; i < 8; i++) {
        float* Cp = C + (size_t)(blockIdx.y * 128 + ty * 8 + i) * N + blockIdx.x * 128 + tx * 8;
        *(float4*)(Cp)     = make_float4(acc[i][0], acc[i][1], acc[i][2], acc[i][3]);
        *(float4*)(Cp + 4) = make_float4(acc[i][4], acc[i][5], acc[i][6], acc[i][7]);
    }
}

// ---------------------------------------------------------------------------
// RoPE in-place on g_Q (with 1/sqrt(hd) folded in) and g_K.
// One block per sequence position; cos/sin computed once into smem.
// ---------------------------------------------------------------------------
__global__ void rope_kernel(const int* __restrict__ pos) {
    __shared__ float cs[64], sn[64];
    int s = blockIdx.x;
    float p = (float)pos[s];
    if (threadIdx.x < 64) {
        int d = threadIdx.x;
        float freq = (float)pow(10000.0, -(double)d / 64.0);  // inv_freq[d]
        float ang = p * freq;                                 // fp32 like reference
        sincosf(ang, &sn[d], &cs[d]);
    }
    __syncthreads();
    const float scale = 0.08838834764831845f;  // 1/sqrt(128)
    for (int item = threadIdx.x; item < (NH + NKV) * 64; item += blockDim.x) {
        int head = item >> 6;
        int d    = item & 63;
        float* base;
        if (head < NH) base = g_Q + (size_t)s * HID + head * HD;
        else           base = g_K + (size_t)s * KVD + (head - NH) * HD;
        float x1 = base[d], x2 = base[d + 64];
        float c = cs[d], si = sn[d];
        float o1 = x1 * c - x2 * si;   // q*cos + rotate_half(q)*sin, first half
        float o2 = x2 * c + x1 * si;   // second half
        if (head < NH) { o1 *= scale; o2 *= scale; }
        base[d]      = o1;
        base[d + 64] = o2;
    }
}

// ---------------------------------------------------------------------------
// Scores: P[h, qi, ki] = Q[h,qi,:] . K[kv,ki,:]   (Q already scaled)
// 64x64 tile over hd=128, BK=16, 256 threads, 4x4 microtile.
// Upper-triangular tiles skipped; no masking needed (softmax handles extent).
// ---------------------------------------------------------------------------
__global__ __launch_bounds__(256) void scores_kernel() {
    int kb = blockIdx.x, qb = blockIdx.y, h = blockIdx.z;
    if (kb > qb) return;
    __shared__ float Qs[16][64];
    __shared__ float Ks[16][64];
    int tid = threadIdx.x;
    int row = tid >> 2;             // 0..63
    int c4  = (tid & 3) << 2;       // 0,4,8,12
    const float* Qp = g_Q + (size_t)(qb * 64 + row) * HID + h * HD + c4;
    const float* Kp = g_K + (size_t)(kb * 64 + row) * KVD + (h >> 2) * HD + c4;
    int ty = tid >> 4, tx = tid & 15;
    float acc[4][4] = {};
    for (int k0 = 0; k0 < HD; k0 += 16) {
        float4 qv = *(const float4*)(Qp + k0);
        float4 kv = *(const float4*)(Kp + k0);
        Qs[c4 + 0][row] = qv.x; Qs[c4 + 1][row] = qv.y;
        Qs[c4 + 2][row] = qv.z; Qs[c4 + 3][row] = qv.w;
        Ks[c4 + 0][row] = kv.x; Ks[c4 + 1][row] = kv.y;
        Ks[c4 + 2][row] = kv.z; Ks[c4 + 3][row] = kv.w;
        __syncthreads();
#pragma unroll
        for (int kk = 0; kk < 16; kk++) {
            float a[4], b[4];
            *(float4*)a = *(const float4*)&Qs[kk][ty * 4];
            *(float4*)b = *(const float4*)&Ks[kk][tx * 4];
#pragma unroll
            for (int i = 0; i < 4; i++)
#pragma unroll
                for (int j = 0; j < 4; j++)
                    acc[i][j] += a[i] * b[j];
        }
        __syncthreads();
    }
    float* Pp = g_P + (size_t)h * SQ * SQ;
#pragma unroll
    for (int i = 0; i < 4; i++) {
        float* o = Pp + (size_t)(qb * 64 + ty * 4 + i) * SQ + kb * 64 + tx * 4;
        *(float4*)o = make_float4(acc[i][0], acc[i][1], acc[i][2], acc[i][3]);
    }
}

// ---------------------------------------------------------------------------
// Row softmax over cols [0, q]; zero-fill [q+1, roundup64(q+1)) so the PV
// GEMM can read whole 64-wide tiles without masking.
// ---------------------------------------------------------------------------
__global__ __launch_bounds__(128) void softmax_kernel() {
    int q = blockIdx.x, h = blockIdx.y;
    float* row = g_P + ((size_t)h * SQ + q) * SQ;
    int n  = q + 1;
    int kw = ((q >> 6) + 1) << 6;
    int tid = threadIdx.x;
    __shared__ float red[128];

    float vals[16];
    float m = -FLT_MAX;
    int cnt = 0;
    for (int i = tid; i < n; i += 128) {
        float v = row[i];
        vals[cnt++] = v;
        m = fmaxf(m, v);
    }
    red[tid] = m; __syncthreads();
    for (int s = 64; s > 0; s >>= 1) {
        if (tid < s) red[tid] = fmaxf(red[tid], red[tid + s]);
        __syncthreads();
    }
    m = red[0]; __syncthreads();

    float sum = 0.f;
    for (int c = 0; c < cnt; c++) {
        float e = expf(vals[c] - m);
        vals[c] = e;
        sum += e;
    }
    red[tid] = sum; __syncthreads();
    for (int s = 64; s > 0; s >>= 1) {
        if (tid < s) red[tid] += red[tid + s];
        __syncthreads();
    }
    float inv = 1.f / red[0];

    cnt = 0;
    for (int i = tid; i < n; i += 128) row[i] = vals[cnt++] * inv;
    for (int i = n + tid; i < kw; i += 128) row[i] = 0.f;
}

// ---------------------------------------------------------------------------
// PV: attn[h, qi, d] = sum_k P[h,qi,k] * V[kv,k,d]
// Output tile 64x128, 128 threads, 8x8 microtile; kb runs 0..qb (causal).
// Writes directly into [s, h*128+d] layout.
// ---------------------------------------------------------------------------
__global__ __launch_bounds__(128) void pv_kernel() {
    int qb = blockIdx.x, h = blockIdx.y;
    __shared__ float Ps[64][64];    // [k][q]
    __shared__ float Vs[64][128];   // [k][d]
    int tid = threadIdx.x;
    int ty = tid >> 4, tx = tid & 15;   // rows ty*8.., cols tx*8..
    float acc[8][8] = {};
    const float* Pbase = g_P + (size_t)h * SQ * SQ + (size_t)qb * 64 * SQ;
    const float* Vbase = g_V + (h >> 2) * HD;

    int pq  = tid >> 1;
    int pc0 = (tid & 1) * 32;
    int vr  = tid >> 1;
    int vc0 = (tid & 1) * 64;

    for (int kb = 0; kb <= qb; kb++) {
        // load P tile [64 q][64 k] transposed into Ps[k][q]
        const float* pp = Pbase + (size_t)pq * SQ + kb * 64 + pc0;
#pragma unroll
        for (int v = 0; v < 8; v++) {
            float4 t = *(const float4*)(pp + v * 4);
            Ps[pc0 + v * 4 + 0][pq] = t.x;
            Ps[pc0 + v * 4 + 1][pq] = t.y;
            Ps[pc0 + v * 4 + 2][pq] = t.z;
            Ps[pc0 + v * 4 + 3][pq] = t.w;
        }
        // load V tile [64 k][128 d]
        const float4* vp = (const float4*)(Vbase + (size_t)(kb * 64 + vr) * KVD + vc0);
        float4* vs = (float4*)&Vs[vr][vc0];
#pragma unroll
        for (int v = 0; v < 16; v++) vs[v] = vp[v];
        __syncthreads();
#pragma unroll 4
        for (int kk = 0; kk < 64; kk++) {
            float a[8], b[8];
            *(float4*)(a)     = *(const float4*)&Ps[kk][ty * 8];
            *(float4*)(a + 4) = *(const float4*)&Ps[kk][ty * 8 + 4];
            *(float4*)(b)     = *(const float4*)&Vs[kk][tx * 8];
            *(float4*)(b + 4) = *(const float4*)&Vs[kk][tx * 8 + 4];
#pragma unroll
            for (int i = 0; i < 8; i++)
#pragma unroll
                for (int j = 0; j < 8; j++)
                    acc[i][j] += a[i] * b[j];
        }
        __syncthreads();
    }
#pragma unroll
    for (int i = 0; i < 8; i++) {
        float* o = g_A + (size_t)(qb * 64 + ty * 8 + i) * HID + h * HD + tx * 8;
        *(float4*)(o)     = make_float4(acc[i][0], acc[i][1], acc[i][2], acc[i][3]);
        *(float4*)(o + 4) = make_float4(acc[i][4], acc[i][5], acc[i][6], acc[i][7]);
    }
}

// ---------------------------------------------------------------------------
extern "C" void kernel_launch(void* const* d_in, const int* in_sizes, int n_in,
                              void* d_out, int out_size) {
    (void)in_sizes; (void)n_in; (void)out_size;
    const float* X   = (const float*)d_in[0];
    const int*   pos = (const int*)d_in[1];
    const float* Wq  = (const float*)d_in[2];
    const float* Wk  = (const float*)d_in[3];
    const float* Wv  = (const float*)d_in[4];
    const float* Wo  = (const float*)d_in[5];
    float* out = (float*)d_out;

    float *Qd, *Kd, *Vd, *Ad;
    cudaGetSymbolAddress((void**)&Qd, g_Q);
    cudaGetSymbolAddress((void**)&Kd, g_K);
    cudaGetSymbolAddress((void**)&Vd, g_V);
    cudaGetSymbolAddress((void**)&Ad, g_A);

    dim3 gBig(HID / 128, SQ / 128);   // (32, 16)
    dim3 gKV (KVD / 128, SQ / 128);   // (8, 16)

    gemm_nt<<<gBig, 256>>>(X, Wq, Qd, SQ, HID, HID);
    gemm_nt<<<gKV,  256>>>(X, Wk, Kd, SQ, KVD, HID);
    gemm_nt<<<gKV,  256>>>(X, Wv, Vd, SQ, KVD, HID);
    rope_kernel<<<SQ, 256>>>(pos);
    scores_kernel<<<dim3(SQ / 64, SQ / 64, NH), 256>>>();
    softmax_kernel<<<dim3(SQ, NH), 128>>>();
    pv_kernel<<<dim3(SQ / 64, NH), 128>>>();
    gemm_nt<<<gBig, 256>>>(Ad, Wo, out, SQ, HID, HID);
}

// round 4
// speedup vs baseline: 2.0390x; 2.0390x over previous
#include <cuda_runtime.h>
#include <math.h>
#include <float.h>
#include <stdint.h>

#define SQ   2048
#define HID  4096
#define NH   32
#define NKV  8
#define HD   128
#define KVD  1024   // NKV * HD

// Scratch (allocation-free rule: __device__ globals)
__device__ float g_Q[SQ * HID];                 // 32 MB  (post-RoPE, scaled)
__device__ float g_K[SQ * KVD];                 // 8 MB
__device__ float g_V[SQ * KVD];                 // 8 MB
__device__ float g_A[SQ * HID];                 // 32 MB  (attention out, tf32-rounded)
__device__ float g_P[(size_t)NH * SQ * SQ];     // 512 MB (scores -> probs)
// tf32-rounded copies of GEMM inputs
__device__ float g_Xc[SQ * HID];                // 32 MB
__device__ float g_Wqc[HID * HID];              // 64 MB
__device__ float g_Wkc[KVD * HID];              // 16 MB
__device__ float g_Wvc[KVD * HID];              // 16 MB
__device__ float g_Woc[HID * HID];              // 64 MB

__device__ __forceinline__ float rna_tf32(float x) {
    uint32_t u;
    asm("cvt.rna.tf32.f32 %0, %1;" : "=r"(u) : "f"(x));
    return __uint_as_float(u);
}
__device__ __forceinline__ uint32_t smem_u32(const void* p) {
    uint32_t a;
    asm("{ .reg .u64 t; cvta.to.shared.u64 t, %1; cvt.u32.u64 %0, t; }" : "=r"(a) : "l"(p));
    return a;
}
__device__ __forceinline__ void cp_async16(uint32_t dst, const void* src) {
    asm volatile("cp.async.cg.shared.global [%0], [%1], 16;" :: "r"(dst), "l"(src) : "memory");
}
#define CP_COMMIT() asm volatile("cp.async.commit_group;" ::: "memory")

__device__ __forceinline__ void mma_tf32(float* c, const uint32_t* a, const uint32_t* b) {
    asm volatile(
        "mma.sync.aligned.m16n8k8.row.col.f32.tf32.tf32.f32 "
        "{%0,%1,%2,%3}, {%4,%5,%6,%7}, {%8,%9}, {%0,%1,%2,%3};"
        : "+f"(c[0]), "+f"(c[1]), "+f"(c[2]), "+f"(c[3])
        : "r"(a[0]), "r"(a[1]), "r"(a[2]), "r"(a[3]), "r"(b[0]), "r"(b[1]));
}

// ---------------------------------------------------------------------------
// Round fp32 -> tf32 (RN) copy
// ---------------------------------------------------------------------------
__global__ void round_tf32_kernel(const float4* __restrict__ in,
                                  float4* __restrict__ out, int n4) {
    int i = blockIdx.x * blockDim.x + threadIdx.x;
    if (i < n4) {
        float4 v = in[i];
        v.x = rna_tf32(v.x); v.y = rna_tf32(v.y);
        v.z = rna_tf32(v.z); v.w = rna_tf32(v.w);
        out[i] = v;
    }
}

// ---------------------------------------------------------------------------
// Tensor-core tf32 GEMM: C[M,N] = A[M,K] @ B[N,K]^T (row-major, K-contiguous,
// inputs pre-rounded to tf32). CTA 128x128, 8 warps (2x4), warp tile 64x32,
// K staged 16 floats, double-buffered cp.async. Smem stride 20 -> the
// 8-row x 4-kcol fragment pattern covers all 32 banks (conflict-free).
// ---------------------------------------------------------------------------
#define SMS 20   // smem row stride in floats

__global__ __launch_bounds__(256) void gemm_mma(const float* __restrict__ A,
                                                const float* __restrict__ B,
                                                float* __restrict__ C,
                                                int M, int N, int K) {
    __shared__ float As[2][128][SMS];
    __shared__ float Bs[2][128][SMS];
    int tid = threadIdx.x, lane = tid & 31, wid = tid >> 5;
    int wm = (wid >> 2) * 64;     // 0 or 64
    int wn = (wid & 3) * 32;      // 0..96
    int g = lane >> 2, t = lane & 3;
    int m0 = blockIdx.y * 128, n0 = blockIdx.x * 128;

    // staging: thread covers 8 consecutive floats of one row
    int lrow = tid >> 1, lcol = (tid & 1) * 8;
    const float* Ag = A + (size_t)(m0 + lrow) * K + lcol;
    const float* Bg = B + (size_t)(n0 + lrow) * K + lcol;
    uint32_t sA[2], sB[2];
    sA[0] = smem_u32(&As[0][lrow][lcol]); sA[1] = smem_u32(&As[1][lrow][lcol]);
    sB[0] = smem_u32(&Bs[0][lrow][lcol]); sB[1] = smem_u32(&Bs[1][lrow][lcol]);

    float acc[4][4][4] = {};
    int S = K >> 4;

#define LOAD_STAGE(st) do { \
        int _b = (st) & 1; \
        const float* _a = Ag + (st) * 16; \
        const float* _bg = Bg + (st) * 16; \
        cp_async16(sA[_b],      _a);      cp_async16(sA[_b] + 16, _a + 4); \
        cp_async16(sB[_b],      _bg);     cp_async16(sB[_b] + 16, _bg + 4); \
        CP_COMMIT(); \
    } while (0)

    LOAD_STAGE(0);
    LOAD_STAGE(1);

    for (int kt = 0; kt < S; kt++) {
        if (kt < S - 1) asm volatile("cp.async.wait_group 1;" ::: "memory");
        else            asm volatile("cp.async.wait_group 0;" ::: "memory");
        __syncthreads();
        int buf = kt & 1;
#pragma unroll
        for (int kk = 0; kk < 16; kk += 8) {
            uint32_t a[4][4], b[4][2];
#pragma unroll
            for (int i = 0; i < 4; i++) {
                a[i][0] = __float_as_uint(As[buf][wm + i * 16 + g][kk + t]);
                a[i][1] = __float_as_uint(As[buf][wm + i * 16 + g + 8][kk + t]);
                a[i][2] = __float_as_uint(As[buf][wm + i * 16 + g][kk + t + 4]);
                a[i][3] = __float_as_uint(As[buf][wm + i * 16 + g + 8][kk + t + 4]);
            }
#pragma unroll
            for (int j = 0; j < 4; j++) {
                b[j][0] = __float_as_uint(Bs[buf][wn + j * 8 + g][kk + t]);
                b[j][1] = __float_as_uint(Bs[buf][wn + j * 8 + g][kk + t + 4]);
            }
#pragma unroll
            for (int i = 0; i < 4; i++)
#pragma unroll
                for (int j = 0; j < 4; j++)
                    mma_tf32(acc[i][j], a[i], b[j]);
        }
        __syncthreads();
        if (kt + 2 < S) LOAD_STAGE(kt + 2);
    }
#undef LOAD_STAGE

#pragma unroll
    for (int i = 0; i < 4; i++) {
#pragma unroll
        for (int j = 0; j < 4; j++) {
            int r0 = m0 + wm + i * 16 + g;
            int cc = n0 + wn + j * 8 + t * 2;
            *(float2*)(C + (size_t)r0 * N + cc)       = make_float2(acc[i][j][0], acc[i][j][1]);
            *(float2*)(C + (size_t)(r0 + 8) * N + cc) = make_float2(acc[i][j][2], acc[i][j][3]);
        }
    }
}

// ---------------------------------------------------------------------------
// RoPE in-place on g_Q (with 1/sqrt(hd) folded in) and g_K.
// ---------------------------------------------------------------------------
__global__ void rope_kernel(const int* __restrict__ pos) {
    __shared__ float cs[64], sn[64];
    int s = blockIdx.x;
    float p = (float)pos[s];
    if (threadIdx.x < 64) {
        int d = threadIdx.x;
        float freq = (float)pow(10000.0, -(double)d / 64.0);
        float ang = p * freq;
        sincosf(ang, &sn[d], &cs[d]);
    }
    __syncthreads();
    const float scale = 0.08838834764831845f;  // 1/sqrt(128)
    for (int item = threadIdx.x; item < (NH + NKV) * 64; item += blockDim.x) {
        int head = item >> 6;
        int d    = item & 63;
        float* base;
        if (head < NH) base = g_Q + (size_t)s * HID + head * HD;
        else           base = g_K + (size_t)s * KVD + (head - NH) * HD;
        float x1 = base[d], x2 = base[d + 64];
        float c = cs[d], si = sn[d];
        float o1 = x1 * c - x2 * si;
        float o2 = x2 * c + x1 * si;
        if (head < NH) { o1 *= scale; o2 *= scale; }
        base[d]      = o1;
        base[d + 64] = o2;
    }
}

// ---------------------------------------------------------------------------
// Scores: P[h, qi, ki] = Q[h,qi,:] . K[kv,ki,:]  (fp32)
// ---------------------------------------------------------------------------
__global__ __launch_bounds__(256) void scores_kernel() {
    int kb = blockIdx.x, qb = blockIdx.y, h = blockIdx.z;
    if (kb > qb) return;
    __shared__ float Qs[16][64];
    __shared__ float Ks[16][64];
    int tid = threadIdx.x;
    int row = tid >> 2;
    int c4  = (tid & 3) << 2;
    const float* Qp = g_Q + (size_t)(qb * 64 + row) * HID + h * HD + c4;
    const float* Kp = g_K + (size_t)(kb * 64 + row) * KVD + (h >> 2) * HD + c4;
    int ty = tid >> 4, tx = tid & 15;
    float acc[4][4] = {};
    for (int k0 = 0; k0 < HD; k0 += 16) {
        float4 qv = *(const float4*)(Qp + k0);
        float4 kv = *(const float4*)(Kp + k0);
        Qs[c4 + 0][row] = qv.x; Qs[c4 + 1][row] = qv.y;
        Qs[c4 + 2][row] = qv.z; Qs[c4 + 3][row] = qv.w;
        Ks[c4 + 0][row] = kv.x; Ks[c4 + 1][row] = kv.y;
        Ks[c4 + 2][row] = kv.z; Ks[c4 + 3][row] = kv.w;
        __syncthreads();
#pragma unroll
        for (int kk = 0; kk < 16; kk++) {
            float a[4], b[4];
            *(float4*)a = *(const float4*)&Qs[kk][ty * 4];
            *(float4*)b = *(const float4*)&Ks[kk][tx * 4];
#pragma unroll
            for (int i = 0; i < 4; i++)
#pragma unroll
                for (int j = 0; j < 4; j++)
                    acc[i][j] += a[i] * b[j];
        }
        __syncthreads();
    }
    float* Pp = g_P + (size_t)h * SQ * SQ;
#pragma unroll
    for (int i = 0; i < 4; i++) {
        float* o = Pp + (size_t)(qb * 64 + ty * 4 + i) * SQ + kb * 64 + tx * 4;
        *(float4*)o = make_float4(acc[i][0], acc[i][1], acc[i][2], acc[i][3]);
    }
}

// ---------------------------------------------------------------------------
// Row softmax over cols [0, q]; zero-fill to 64-wide boundary.
// ---------------------------------------------------------------------------
__global__ __launch_bounds__(128) void softmax_kernel() {
    int q = blockIdx.x, h = blockIdx.y;
    float* row = g_P + ((size_t)h * SQ + q) * SQ;
    int n  = q + 1;
    int kw = ((q >> 6) + 1) << 6;
    int tid = threadIdx.x;
    __shared__ float red[128];

    float vals[16];
    float m = -FLT_MAX;
    int cnt = 0;
    for (int i = tid; i < n; i += 128) {
        float v = row[i];
        vals[cnt++] = v;
        m = fmaxf(m, v);
    }
    red[tid] = m; __syncthreads();
    for (int s = 64; s > 0; s >>= 1) {
        if (tid < s) red[tid] = fmaxf(red[tid], red[tid + s]);
        __syncthreads();
    }
    m = red[0]; __syncthreads();

    float sum = 0.f;
    for (int c = 0; c < cnt; c++) {
        float e = expf(vals[c] - m);
        vals[c] = e;
        sum += e;
    }
    red[tid] = sum; __syncthreads();
    for (int s = 64; s > 0; s >>= 1) {
        if (tid < s) red[tid] += red[tid + s];
        __syncthreads();
    }
    float inv = 1.f / red[0];

    cnt = 0;
    for (int i = tid; i < n; i += 128) row[i] = vals[cnt++] * inv;
    for (int i = n + tid; i < kw; i += 128) row[i] = 0.f;
}

// ---------------------------------------------------------------------------
// PV: attn[h, qi, d] = sum_k P[h,qi,k] * V[kv,k,d]; output rounded to tf32
// so the O-projection mma GEMM gets RN-rounded input.
// ---------------------------------------------------------------------------
__global__ __launch_bounds__(128) void pv_kernel() {
    int qb = blockIdx.x, h = blockIdx.y;
    __shared__ float Ps[64][64];
    __shared__ float Vs[64][128];
    int tid = threadIdx.x;
    int ty = tid >> 4, tx = tid & 15;
    float acc[8][8] = {};
    const float* Pbase = g_P + (size_t)h * SQ * SQ + (size_t)qb * 64 * SQ;
    const float* Vbase = g_V + (h >> 2) * HD;

    int pq  = tid >> 1;
    int pc0 = (tid & 1) * 32;
    int vr  = tid >> 1;
    int vc0 = (tid & 1) * 64;

    for (int kb = 0; kb <= qb; kb++) {
        const float* pp = Pbase + (size_t)pq * SQ + kb * 64 + pc0;
#pragma unroll
        for (int v = 0; v < 8; v++) {
            float4 t = *(const float4*)(pp + v * 4);
            Ps[pc0 + v * 4 + 0][pq] = t.x;
            Ps[pc0 + v * 4 + 1][pq] = t.y;
            Ps[pc0 + v * 4 + 2][pq] = t.z;
            Ps[pc0 + v * 4 + 3][pq] = t.w;
        }
        const float4* vp = (const float4*)(Vbase + (size_t)(kb * 64 + vr) * KVD + vc0);
        float4* vs = (float4*)&Vs[vr][vc0];
#pragma unroll
        for (int v = 0; v < 16; v++) vs[v] = vp[v];
        __syncthreads();
#pragma unroll 4
        for (int kk = 0; kk < 64; kk++) {
            float a[8], b[8];
            *(float4*)(a)     = *(const float4*)&Ps[kk][ty * 8];
            *(float4*)(a + 4) = *(const float4*)&Ps[kk][ty * 8 + 4];
            *(float4*)(b)     = *(const float4*)&Vs[kk][tx * 8];
            *(float4*)(b + 4) = *(const float4*)&Vs[kk][tx * 8 + 4];
#pragma unroll
            for (int i = 0; i < 8; i++)
#pragma unroll
                for (int j = 0; j < 8; j++)
                    acc[i][j] += a[i] * b[j];
        }
        __syncthreads();
    }
#pragma unroll
    for (int i = 0; i < 8; i++) {
        float* o = g_A + (size_t)(qb * 64 + ty * 8 + i) * HID + h * HD + tx * 8;
        *(float4*)(o)     = make_float4(rna_tf32(acc[i][0]), rna_tf32(acc[i][1]),
                                        rna_tf32(acc[i][2]), rna_tf32(acc[i][3]));
        *(float4*)(o + 4) = make_float4(rna_tf32(acc[i][4]), rna_tf32(acc[i][5]),
                                        rna_tf32(acc[i][6]), rna_tf32(acc[i][7]));
    }
}

// ---------------------------------------------------------------------------
extern "C" void kernel_launch(void* const* d_in, const int* in_sizes, int n_in,
                              void* d_out, int out_size) {
    (void)in_sizes; (void)n_in; (void)out_size;
    const float* X   = (const float*)d_in[0];
    const int*   pos = (const int*)d_in[1];
    const float* Wq  = (const float*)d_in[2];
    const float* Wk  = (const float*)d_in[3];
    const float* Wv  = (const float*)d_in[4];
    const float* Wo  = (const float*)d_in[5];
    float* out = (float*)d_out;

    float *Qd, *Kd, *Vd, *Ad, *Xc, *Wqc, *Wkc, *Wvc, *Woc;
    cudaGetSymbolAddress((void**)&Qd,  g_Q);
    cudaGetSymbolAddress((void**)&Kd,  g_K);
    cudaGetSymbolAddress((void**)&Vd,  g_V);
    cudaGetSymbolAddress((void**)&Ad,  g_A);
    cudaGetSymbolAddress((void**)&Xc,  g_Xc);
    cudaGetSymbolAddress((void**)&Wqc, g_Wqc);
    cudaGetSymbolAddress((void**)&Wkc, g_Wkc);
    cudaGetSymbolAddress((void**)&Wvc, g_Wvc);
    cudaGetSymbolAddress((void**)&Woc, g_Woc);

    // Round all GEMM inputs fp32 -> tf32 (RN)
    {
        int n4;
        n4 = SQ * HID / 4;
        round_tf32_kernel<<<(n4 + 255) / 256, 256>>>((const float4*)X,  (float4*)Xc,  n4);
        n4 = HID * HID / 4;
        round_tf32_kernel<<<(n4 + 255) / 256, 256>>>((const float4*)Wq, (float4*)Wqc, n4);
        n4 = KVD * HID / 4;
        round_tf32_kernel<<<(n4 + 255) / 256, 256>>>((const float4*)Wk, (float4*)Wkc, n4);
        round_tf32_kernel<<<(n4 + 255) / 256, 256>>>((const float4*)Wv, (float4*)Wvc, n4);
        n4 = HID * HID / 4;
        round_tf32_kernel<<<(n4 + 255) / 256, 256>>>((const float4*)Wo, (float4*)Woc, n4);
    }

    dim3 gBig(HID / 128, SQ / 128);   // (32, 16)
    dim3 gKV (KVD / 128, SQ / 128);   // (8, 16)

    gemm_mma<<<gBig, 256>>>(Xc, Wqc, Qd, SQ, HID, HID);
    gemm_mma<<<gKV,  256>>>(Xc, Wkc, Kd, SQ, KVD, HID);
    gemm_mma<<<gKV,  256>>>(Xc, Wvc, Vd, SQ, KVD, HID);
    rope_kernel<<<SQ, 256>>>(pos);
    scores_kernel<<<dim3(SQ / 64, SQ / 64, NH), 256>>>();
    softmax_kernel<<<dim3(SQ, NH), 128>>>();
    pv_kernel<<<dim3(SQ / 64, NH), 128>>>();
    gemm_mma<<<gBig, 256>>>(Ad, Woc, out, SQ, HID, HID);
}

// round 5
// speedup vs baseline: 2.8576x; 1.4015x over previous
#include <cuda_runtime.h>
#include <math.h>
#include <float.h>
#include <stdint.h>

#define SQ   2048
#define HID  4096
#define NH   32
#define NKV  8
#define HD   128
#define KVD  1024   // NKV * HD

// Scratch (allocation-free rule: __device__ globals)
__device__ float g_Q[SQ * HID];                 // 32 MB  (post-RoPE, scaled, tf32)
__device__ float g_K[SQ * KVD];                 // 8 MB   (post-RoPE, tf32)
__device__ float g_V[SQ * KVD];                 // 8 MB   (tf32)
__device__ float g_Vt[KVD * SQ];                // 8 MB   (V transposed [kv*HD+d][s], tf32)
__device__ float g_A[SQ * HID];                 // 32 MB  (attention out, tf32)
__device__ float g_P[(size_t)NH * SQ * SQ];     // 512 MB (scores -> probs, tf32 after softmax)
// tf32-rounded copies of GEMM inputs
__device__ float g_Xc[SQ * HID];                // 32 MB
__device__ float g_Wqc[HID * HID];              // 64 MB
__device__ float g_Wkc[KVD * HID];              // 16 MB
__device__ float g_Wvc[KVD * HID];              // 16 MB
__device__ float g_Woc[HID * HID];              // 64 MB

__device__ __forceinline__ float rna_tf32(float x) {
    uint32_t u;
    asm("cvt.rna.tf32.f32 %0, %1;" : "=r"(u) : "f"(x));
    return __uint_as_float(u);
}
__device__ __forceinline__ uint32_t smem_u32(const void* p) {
    uint32_t a;
    asm("{ .reg .u64 t; cvta.to.shared.u64 t, %1; cvt.u32.u64 %0, t; }" : "=r"(a) : "l"(p));
    return a;
}
__device__ __forceinline__ void cp_async16(uint32_t dst, const void* src) {
    asm volatile("cp.async.cg.shared.global [%0], [%1], 16;" :: "r"(dst), "l"(src) : "memory");
}
#define CP_COMMIT() asm volatile("cp.async.commit_group;" ::: "memory")

__device__ __forceinline__ void mma_tf32(float* c, const uint32_t* a, const uint32_t* b) {
    asm volatile(
        "mma.sync.aligned.m16n8k8.row.col.f32.tf32.tf32.f32 "
        "{%0,%1,%2,%3}, {%4,%5,%6,%7}, {%8,%9}, {%0,%1,%2,%3};"
        : "+f"(c[0]), "+f"(c[1]), "+f"(c[2]), "+f"(c[3])
        : "r"(a[0]), "r"(a[1]), "r"(a[2]), "r"(a[3]), "r"(b[0]), "r"(b[1]));
}

#define SMS 20   // smem row stride in floats (conflict-free for the frag pattern)

// ---------------------------------------------------------------------------
// Round fp32 -> tf32 (RN) copy
// ---------------------------------------------------------------------------
__global__ void round_tf32_kernel(const float4* __restrict__ in,
                                  float4* __restrict__ out, int n4) {
    int i = blockIdx.x * blockDim.x + threadIdx.x;
    if (i < n4) {
        float4 v = in[i];
        v.x = rna_tf32(v.x); v.y = rna_tf32(v.y);
        v.z = rna_tf32(v.z); v.w = rna_tf32(v.w);
        out[i] = v;
    }
}

// ---------------------------------------------------------------------------
// Shared MMA mainloop machinery: CTA 128x128 tile, 8 warps (2x4), warp tile
// 64x32, K staged 16 floats, double-buffered cp.async.
// ---------------------------------------------------------------------------
#define MMA_LOAD_STAGE(st) do { \
        int _b = (st) & 1; \
        const float* _a = Ag + (st) * 16; \
        const float* _bg = Bg + (st) * 16; \
        cp_async16(sA[_b],      _a);      cp_async16(sA[_b] + 16, _a + 4); \
        cp_async16(sB[_b],      _bg);     cp_async16(sB[_b] + 16, _bg + 4); \
        CP_COMMIT(); \
    } while (0)

#define MMA_MAINLOOP(S) \
    MMA_LOAD_STAGE(0); \
    MMA_LOAD_STAGE(1); \
    for (int kt = 0; kt < (S); kt++) { \
        if (kt < (S) - 1) asm volatile("cp.async.wait_group 1;" ::: "memory"); \
        else              asm volatile("cp.async.wait_group 0;" ::: "memory"); \
        __syncthreads(); \
        int buf = kt & 1; \
        _Pragma("unroll") \
        for (int kk = 0; kk < 16; kk += 8) { \
            uint32_t a[4][4], b[4][2]; \
            _Pragma("unroll") \
            for (int i = 0; i < 4; i++) { \
                a[i][0] = __float_as_uint(As[buf][wm + i * 16 + g][kk + t]); \
                a[i][1] = __float_as_uint(As[buf][wm + i * 16 + g + 8][kk + t]); \
                a[i][2] = __float_as_uint(As[buf][wm + i * 16 + g][kk + t + 4]); \
                a[i][3] = __float_as_uint(As[buf][wm + i * 16 + g + 8][kk + t + 4]); \
            } \
            _Pragma("unroll") \
            for (int j = 0; j < 4; j++) { \
                b[j][0] = __float_as_uint(Bs[buf][wn + j * 8 + g][kk + t]); \
                b[j][1] = __float_as_uint(Bs[buf][wn + j * 8 + g][kk + t + 4]); \
            } \
            _Pragma("unroll") \
            for (int i = 0; i < 4; i++) \
                _Pragma("unroll") \
                for (int j = 0; j < 4; j++) \
                    mma_tf32(acc[i][j], a[i], b[j]); \
        } \
        __syncthreads(); \
        if (kt + 2 < (S)) MMA_LOAD_STAGE(kt + 2); \
    }

#define MMA_PROLOG() \
    __shared__ float As[2][128][SMS]; \
    __shared__ float Bs[2][128][SMS]; \
    int tid = threadIdx.x, lane = tid & 31, wid = tid >> 5; \
    int wm = (wid >> 2) * 64; \
    int wn = (wid & 3) * 32; \
    int g = lane >> 2, t = lane & 3; \
    int lrow = tid >> 1, lcol = (tid & 1) * 8; \
    uint32_t sA[2], sB[2]; \
    sA[0] = smem_u32(&As[0][lrow][lcol]); sA[1] = smem_u32(&As[1][lrow][lcol]); \
    sB[0] = smem_u32(&Bs[0][lrow][lcol]); sB[1] = smem_u32(&Bs[1][lrow][lcol]); \
    float acc[4][4][4] = {};

// ---------------------------------------------------------------------------
// Projection GEMM: C[M,N] = A[M,K] @ B[N,K]^T (row-major, K-contiguous).
// roundC: round outputs to tf32 (for V, whose consumer is an mma).
// ---------------------------------------------------------------------------
__global__ __launch_bounds__(256) void gemm_mma(const float* __restrict__ A,
                                                const float* __restrict__ B,
                                                float* __restrict__ C,
                                                int M, int N, int K, int roundC) {
    MMA_PROLOG();
    int m0 = blockIdx.y * 128, n0 = blockIdx.x * 128;
    const float* Ag = A + (size_t)(m0 + lrow) * K + lcol;
    const float* Bg = B + (size_t)(n0 + lrow) * K + lcol;
    int S = K >> 4;
    MMA_MAINLOOP(S);
#pragma unroll
    for (int i = 0; i < 4; i++) {
#pragma unroll
        for (int j = 0; j < 4; j++) {
            int r0 = m0 + wm + i * 16 + g;
            int cc = n0 + wn + j * 8 + t * 2;
            float4 v = make_float4(acc[i][j][0], acc[i][j][1], acc[i][j][2], acc[i][j][3]);
            if (roundC) {
                v.x = rna_tf32(v.x); v.y = rna_tf32(v.y);
                v.z = rna_tf32(v.z); v.w = rna_tf32(v.w);
            }
            *(float2*)(C + (size_t)r0 * N + cc)       = make_float2(v.x, v.y);
            *(float2*)(C + (size_t)(r0 + 8) * N + cc) = make_float2(v.z, v.w);
        }
    }
}

// ---------------------------------------------------------------------------
// Scores: P[h, q, k] = Q[h,q,:] . K[kv,k,:]   (tf32 mma, causal tile skip)
// ---------------------------------------------------------------------------
__global__ __launch_bounds__(256) void scores_mma() {
    int kb = blockIdx.x, qb = blockIdx.y, h = blockIdx.z;
    if (kb > qb) return;
    MMA_PROLOG();
    const float* Ag = g_Q + (size_t)(qb * 128 + lrow) * HID + h * HD + lcol;
    const float* Bg = g_K + (size_t)(kb * 128 + lrow) * KVD + (h >> 2) * HD + lcol;
    MMA_MAINLOOP(8);   // K = 128
    float* Pp = g_P + (size_t)h * SQ * SQ;
#pragma unroll
    for (int i = 0; i < 4; i++) {
#pragma unroll
        for (int j = 0; j < 4; j++) {
            int r0 = qb * 128 + wm + i * 16 + g;
            int cc = kb * 128 + wn + j * 8 + t * 2;
            *(float2*)(Pp + (size_t)r0 * SQ + cc)       = make_float2(acc[i][j][0], acc[i][j][1]);
            *(float2*)(Pp + (size_t)(r0 + 8) * SQ + cc) = make_float2(acc[i][j][2], acc[i][j][3]);
        }
    }
}

// ---------------------------------------------------------------------------
// PV: attn[h, q, d] = sum_k P[h,q,k] * Vt[kv, d, k]   (tf32 mma)
// K extent = (qb+1)*128 (P zero-filled to 128 boundary by softmax).
// ---------------------------------------------------------------------------
__global__ __launch_bounds__(256) void pv_mma() {
    int qb = blockIdx.x, h = blockIdx.y;
    MMA_PROLOG();
    const float* Ag = g_P + (size_t)h * SQ * SQ + (size_t)(qb * 128 + lrow) * SQ + lcol;
    const float* Bg = g_Vt + (size_t)((h >> 2) * HD + lrow) * SQ + lcol;
    int S = (qb + 1) * 8;
    MMA_MAINLOOP(S);
#pragma unroll
    for (int i = 0; i < 4; i++) {
#pragma unroll
        for (int j = 0; j < 4; j++) {
            int r0 = qb * 128 + wm + i * 16 + g;
            int cc = h * HD + wn + j * 8 + t * 2;
            *(float2*)(g_A + (size_t)r0 * HID + cc) =
                make_float2(rna_tf32(acc[i][j][0]), rna_tf32(acc[i][j][1]));
            *(float2*)(g_A + (size_t)(r0 + 8) * HID + cc) =
                make_float2(rna_tf32(acc[i][j][2]), rna_tf32(acc[i][j][3]));
        }
    }
}

// ---------------------------------------------------------------------------
// RoPE in-place on g_Q (1/sqrt(hd) folded in) and g_K; outputs tf32-rounded.
// ---------------------------------------------------------------------------
__global__ void rope_kernel(const int* __restrict__ pos) {
    __shared__ float cs[64], sn[64];
    int s = blockIdx.x;
    float p = (float)pos[s];
    if (threadIdx.x < 64) {
        int d = threadIdx.x;
        float freq = (float)pow(10000.0, -(double)d / 64.0);
        float ang = p * freq;
        sincosf(ang, &sn[d], &cs[d]);
    }
    __syncthreads();
    const float scale = 0.08838834764831845f;  // 1/sqrt(128)
    for (int item = threadIdx.x; item < (NH + NKV) * 64; item += blockDim.x) {
        int head = item >> 6;
        int d    = item & 63;
        float* base;
        if (head < NH) base = g_Q + (size_t)s * HID + head * HD;
        else           base = g_K + (size_t)s * KVD + (head - NH) * HD;
        float x1 = base[d], x2 = base[d + 64];
        float c = cs[d], si = sn[d];
        float o1 = x1 * c - x2 * si;
        float o2 = x2 * c + x1 * si;
        if (head < NH) { o1 *= scale; o2 *= scale; }
        base[d]      = rna_tf32(o1);
        base[d + 64] = rna_tf32(o2);
    }
}

// ---------------------------------------------------------------------------
// V transpose: g_Vt[kv*HD + d][s] = g_V[s][kv*HD + d]   (already tf32)
// ---------------------------------------------------------------------------
__global__ __launch_bounds__(256) void transpose_v_kernel() {
    __shared__ float tb[32][33];
    int s0 = blockIdx.x * 32, d0 = blockIdx.y * 32, kv = blockIdx.z;
    int tx = threadIdx.x, ty = threadIdx.y;   // (32, 8)
#pragma unroll
    for (int i = 0; i < 4; i++)
        tb[ty + i * 8][tx] = g_V[(size_t)(s0 + ty + i * 8) * KVD + kv * HD + d0 + tx];
    __syncthreads();
#pragma unroll
    for (int i = 0; i < 4; i++)
        g_Vt[(size_t)(kv * HD + d0 + ty + i * 8) * SQ + s0 + tx] = tb[tx][ty + i * 8];
}

// ---------------------------------------------------------------------------
// Row softmax over cols [0, q]; zero-fill to 128-wide boundary; probs tf32.
// ---------------------------------------------------------------------------
__global__ __launch_bounds__(128) void softmax_kernel() {
    int q = blockIdx.x, h = blockIdx.y;
    float* row = g_P + ((size_t)h * SQ + q) * SQ;
    int n  = q + 1;
    int kw = ((q >> 7) + 1) << 7;
    int tid = threadIdx.x;
    __shared__ float red[128];

    float vals[16];
    float m = -FLT_MAX;
    int cnt = 0;
    for (int i = tid; i < n; i += 128) {
        float v = row[i];
        vals[cnt++] = v;
        m = fmaxf(m, v);
    }
    red[tid] = m; __syncthreads();
    for (int s = 64; s > 0; s >>= 1) {
        if (tid < s) red[tid] = fmaxf(red[tid], red[tid + s]);
        __syncthreads();
    }
    m = red[0]; __syncthreads();

    float sum = 0.f;
    for (int c = 0; c < cnt; c++) {
        float e = expf(vals[c] - m);
        vals[c] = e;
        sum += e;
    }
    red[tid] = sum; __syncthreads();
    for (int s = 64; s > 0; s >>= 1) {
        if (tid < s) red[tid] += red[tid + s];
        __syncthreads();
    }
    float inv = 1.f / red[0];

    cnt = 0;
    for (int i = tid; i < n; i += 128) row[i] = rna_tf32(vals[cnt++] * inv);
    for (int i = n + tid; i < kw; i += 128) row[i] = 0.f;
}

// ---------------------------------------------------------------------------
extern "C" void kernel_launch(void* const* d_in, const int* in_sizes, int n_in,
                              void* d_out, int out_size) {
    (void)in_sizes; (void)n_in; (void)out_size;
    const float* X   = (const float*)d_in[0];
    const int*   pos = (const int*)d_in[1];
    const float* Wq  = (const float*)d_in[2];
    const float* Wk  = (const float*)d_in[3];
    const float* Wv  = (const float*)d_in[4];
    const float* Wo  = (const float*)d_in[5];
    float* out = (float*)d_out;

    float *Qd, *Kd, *Vd, *Ad, *Xc, *Wqc, *Wkc, *Wvc, *Woc;
    cudaGetSymbolAddress((void**)&Qd,  g_Q);
    cudaGetSymbolAddress((void**)&Kd,  g_K);
    cudaGetSymbolAddress((void**)&Vd,  g_V);
    cudaGetSymbolAddress((void**)&Ad,  g_A);
    cudaGetSymbolAddress((void**)&Xc,  g_Xc);
    cudaGetSymbolAddress((void**)&Wqc, g_Wqc);
    cudaGetSymbolAddress((void**)&Wkc, g_Wkc);
    cudaGetSymbolAddress((void**)&Wvc, g_Wvc);
    cudaGetSymbolAddress((void**)&Woc, g_Woc);

    // Round all GEMM inputs fp32 -> tf32 (RN)
    {
        int n4;
        n4 = SQ * HID / 4;
        round_tf32_kernel<<<(n4 + 255) / 256, 256>>>((const float4*)X,  (float4*)Xc,  n4);
        n4 = HID * HID / 4;
        round_tf32_kernel<<<(n4 + 255) / 256, 256>>>((const float4*)Wq, (float4*)Wqc, n4);
        n4 = KVD * HID / 4;
        round_tf32_kernel<<<(n4 + 255) / 256, 256>>>((const float4*)Wk, (float4*)Wkc, n4);
        round_tf32_kernel<<<(n4 + 255) / 256, 256>>>((const float4*)Wv, (float4*)Wvc, n4);
        n4 = HID * HID / 4;
        round_tf32_kernel<<<(n4 + 255) / 256, 256>>>((const float4*)Wo, (float4*)Woc, n4);
    }

    dim3 gBig(HID / 128, SQ / 128);   // (32, 16)
    dim3 gKV (KVD / 128, SQ / 128);   // (8, 16)

    gemm_mma<<<gBig, 256>>>(Xc, Wqc, Qd, SQ, HID, HID, 0);
    gemm_mma<<<gKV,  256>>>(Xc, Wkc, Kd, SQ, KVD, HID, 0);
    gemm_mma<<<gKV,  256>>>(Xc, Wvc, Vd, SQ, KVD, HID, 1);   // V rounded for mma
    rope_kernel<<<SQ, 256>>>(pos);
    transpose_v_kernel<<<dim3(SQ / 32, HD / 32, NKV), dim3(32, 8)>>>();
    scores_mma<<<dim3(SQ / 128, SQ / 128, NH), 256>>>();
    softmax_kernel<<<dim3(SQ, NH), 128>>>();
    pv_mma<<<dim3(SQ / 128, NH), 256>>>();
    gemm_mma<<<gBig, 256>>>(Ad, Woc, out, SQ, HID, HID, 0);
}

// round 7
// speedup vs baseline: 3.1029x; 1.0858x over previous
#include <cuda_runtime.h>
#include <math.h>
#include <float.h>
#include <stdint.h>

#define SQ   2048
#define HID  4096
#define NH   32
#define NKV  8
#define HD   128
#define KVD  1024   // NKV * HD

// Scratch (allocation-free rule: __device__ globals)
__device__ float g_Q[SQ * HID];                 // 32 MB  (post-RoPE, scaled, tf32)
__device__ float g_K[SQ * KVD];                 // 8 MB   (post-RoPE, tf32)
__device__ float g_V[SQ * KVD];                 // 8 MB   (tf32)
__device__ float g_Vt[KVD * SQ];                // 8 MB   (V transposed [kv*HD+d][s], tf32)
__device__ float g_A[SQ * HID];                 // 32 MB  (attention out, tf32)
// tf32-rounded copies of GEMM inputs
__device__ float g_Xc[SQ * HID];                // 32 MB
__device__ float g_Wqc[HID * HID];              // 64 MB
__device__ float g_Wkc[KVD * HID];              // 16 MB
__device__ float g_Wvc[KVD * HID];              // 16 MB
__device__ float g_Woc[HID * HID];              // 64 MB

__device__ __forceinline__ float rna_tf32(float x) {
    uint32_t u;
    asm("cvt.rna.tf32.f32 %0, %1;" : "=r"(u) : "f"(x));
    return __uint_as_float(u);
}
__device__ __forceinline__ uint32_t smem_u32(const void* p) {
    uint32_t a;
    asm("{ .reg .u64 t; cvta.to.shared.u64 t, %1; cvt.u32.u64 %0, t; }" : "=r"(a) : "l"(p));
    return a;
}
__device__ __forceinline__ void cp_async16(uint32_t dst, const void* src) {
    asm volatile("cp.async.cg.shared.global [%0], [%1], 16;" :: "r"(dst), "l"(src) : "memory");
}
#define CP_COMMIT() asm volatile("cp.async.commit_group;" ::: "memory")

__device__ __forceinline__ void mma_tf32(float* c, const uint32_t* a, const uint32_t* b) {
    asm volatile(
        "mma.sync.aligned.m16n8k8.row.col.f32.tf32.tf32.f32 "
        "{%0,%1,%2,%3}, {%4,%5,%6,%7}, {%8,%9}, {%0,%1,%2,%3};"
        : "+f"(c[0]), "+f"(c[1]), "+f"(c[2]), "+f"(c[3])
        : "r"(a[0]), "r"(a[1]), "r"(a[2]), "r"(a[3]), "r"(b[0]), "r"(b[1]));
}

#define SMS 20   // smem row stride in floats (conflict-free for the frag pattern)

// ---------------------------------------------------------------------------
// Round fp32 -> tf32 (RN) copy
// ---------------------------------------------------------------------------
__global__ void round_tf32_kernel(const float4* __restrict__ in,
                                  float4* __restrict__ out, int n4) {
    int i = blockIdx.x * blockDim.x + threadIdx.x;
    if (i < n4) {
        float4 v = in[i];
        v.x = rna_tf32(v.x); v.y = rna_tf32(v.y);
        v.z = rna_tf32(v.z); v.w = rna_tf32(v.w);
        out[i] = v;
    }
}

// ---------------------------------------------------------------------------
// Projection GEMM machinery (unchanged, proven): CTA 128x128, 8 warps (2x4),
// warp tile 64x32, K staged 16 floats, double-buffered cp.async.
// ---------------------------------------------------------------------------
#define MMA_LOAD_STAGE(st) do { \
        int _b = (st) & 1; \
        const float* _a = Ag + (st) * 16; \
        const float* _bg = Bg + (st) * 16; \
        cp_async16(sA[_b],      _a);      cp_async16(sA[_b] + 16, _a + 4); \
        cp_async16(sB[_b],      _bg);     cp_async16(sB[_b] + 16, _bg + 4); \
        CP_COMMIT(); \
    } while (0)

#define MMA_MAINLOOP(S) \
    MMA_LOAD_STAGE(0); \
    MMA_LOAD_STAGE(1); \
    for (int kt = 0; kt < (S); kt++) { \
        if (kt < (S) - 1) asm volatile("cp.async.wait_group 1;" ::: "memory"); \
        else              asm volatile("cp.async.wait_group 0;" ::: "memory"); \
        __syncthreads(); \
        int buf = kt & 1; \
        _Pragma("unroll") \
        for (int kk = 0; kk < 16; kk += 8) { \
            uint32_t a[4][4], b[4][2]; \
            _Pragma("unroll") \
            for (int i = 0; i < 4; i++) { \
                a[i][0] = __float_as_uint(As[buf][wm + i * 16 + g][kk + t]); \
                a[i][1] = __float_as_uint(As[buf][wm + i * 16 + g + 8][kk + t]); \
                a[i][2] = __float_as_uint(As[buf][wm + i * 16 + g][kk + t + 4]); \
                a[i][3] = __float_as_uint(As[buf][wm + i * 16 + g + 8][kk + t + 4]); \
            } \
            _Pragma("unroll") \
            for (int j = 0; j < 4; j++) { \
                b[j][0] = __float_as_uint(Bs[buf][wn + j * 8 + g][kk + t]); \
                b[j][1] = __float_as_uint(Bs[buf][wn + j * 8 + g][kk + t + 4]); \
            } \
            _Pragma("unroll") \
            for (int i = 0; i < 4; i++) \
                _Pragma("unroll") \
                for (int j = 0; j < 4; j++) \
                    mma_tf32(acc[i][j], a[i], b[j]); \
        } \
        __syncthreads(); \
        if (kt + 2 < (S)) MMA_LOAD_STAGE(kt + 2); \
    }

__global__ __launch_bounds__(256) void gemm_mma(const float* __restrict__ A,
                                                const float* __restrict__ B,
                                                float* __restrict__ C,
                                                int M, int N, int K, int roundC) {
    __shared__ float As[2][128][SMS];
    __shared__ float Bs[2][128][SMS];
    int tid = threadIdx.x, lane = tid & 31, wid = tid >> 5;
    int wm = (wid >> 2) * 64;
    int wn = (wid & 3) * 32;
    int g = lane >> 2, t = lane & 3;
    int lrow = tid >> 1, lcol = (tid & 1) * 8;
    uint32_t sA[2], sB[2];
    sA[0] = smem_u32(&As[0][lrow][lcol]); sA[1] = smem_u32(&As[1][lrow][lcol]);
    sB[0] = smem_u32(&Bs[0][lrow][lcol]); sB[1] = smem_u32(&Bs[1][lrow][lcol]);
    float acc[4][4][4] = {};

    int m0 = blockIdx.y * 128, n0 = blockIdx.x * 128;
    const float* Ag = A + (size_t)(m0 + lrow) * K + lcol;
    const float* Bg = B + (size_t)(n0 + lrow) * K + lcol;
    int S = K >> 4;
    MMA_MAINLOOP(S);
#pragma unroll
    for (int i = 0; i < 4; i++) {
#pragma unroll
        for (int j = 0; j < 4; j++) {
            int r0 = m0 + wm + i * 16 + g;
            int cc = n0 + wn + j * 8 + t * 2;
            float4 v = make_float4(acc[i][j][0], acc[i][j][1], acc[i][j][2], acc[i][j][3]);
            if (roundC) {
                v.x = rna_tf32(v.x); v.y = rna_tf32(v.y);
                v.z = rna_tf32(v.z); v.w = rna_tf32(v.w);
            }
            *(float2*)(C + (size_t)r0 * N + cc)       = make_float2(v.x, v.y);
            *(float2*)(C + (size_t)(r0 + 8) * N + cc) = make_float2(v.z, v.w);
        }
    }
}

// ---------------------------------------------------------------------------
// Fused flash attention (tf32 mma): per CTA one 128-row q-tile of one head.
// k-tile 64, online softmax, O accumulated in registers.
// Smem: Qs[128][132] | Ks[2][64][132] | Vts[128][68] | Ps[128][68] | red[4*128]
// ---------------------------------------------------------------------------
#define QS_OFF  0
#define KS_OFF  (128 * 132)
#define VT_OFF  (KS_OFF + 2 * 64 * 132)
#define PS_OFF  (VT_OFF + 128 * 68)
#define RED_OFF (PS_OFF + 128 * 68)
#define FL_SMEM ((RED_OFF + 4 * 128) * 4)

__global__ __launch_bounds__(256) void flash_mma() {
    extern __shared__ float sm[];
    float (*Qs)[132]  = (float(*)[132])(sm + QS_OFF);
    float (*Ks)[132]  = (float(*)[132])(sm + KS_OFF);   // [buf*64 + row]
    float (*Vts)[68]  = (float(*)[68])(sm + VT_OFF);
    float (*Ps)[68]   = (float(*)[68])(sm + PS_OFF);
    float* red        = sm + RED_OFF;                   // [wq*128 + row]

    int qb = 15 - (int)blockIdx.x;       // long CTAs first
    int h  = blockIdx.y;
    int tid = threadIdx.x, lane = tid & 31, wid = tid >> 5;
    int wm = (wid >> 2) * 64;            // 0 / 64
    int wq = wid & 3;                    // n-warp index
    int g = lane >> 2, t = lane & 3;
    int kv = h >> 2;

    // ---- prologue: load Q tile (128x128) and K tile 0 ----
#pragma unroll
    for (int j = 0; j < 16; j++) {
        int id = j * 256 + tid;
        int row = id >> 5, c4 = (id & 31) << 2;
        cp_async16(smem_u32(&Qs[row][c4]),
                   g_Q + (size_t)(qb * 128 + row) * HID + h * HD + c4);
    }
    CP_COMMIT();
#pragma unroll
    for (int j = 0; j < 8; j++) {
        int id = j * 256 + tid;
        int row = id >> 5, c4 = (id & 31) << 2;
        cp_async16(smem_u32(&Ks[row][c4]),
                   g_K + (size_t)(row) * KVD + kv * HD + c4);
    }
    CP_COMMIT();
    asm volatile("cp.async.wait_group 0;" ::: "memory");
    __syncthreads();

    float Oacc[4][4][4] = {};
    float mrow[4][2], lrow_[4][2];
#pragma unroll
    for (int i = 0; i < 4; i++) { mrow[i][0] = mrow[i][1] = -1e30f; lrow_[i][0] = lrow_[i][1] = 0.f; }

    int kbmax = 2 * qb + 1;
    for (int kb = 0; kb <= kbmax; kb++) {
        int cur = kb & 1;
        if (kb) {
            asm volatile("cp.async.wait_group 0;" ::: "memory");
            __syncthreads();
        }
        // issue V[kb] (group), then K[kb+1] (group)
#pragma unroll
        for (int j = 0; j < 8; j++) {
            int id = j * 256 + tid;
            int row = id >> 4, c4 = (id & 15) << 2;
            cp_async16(smem_u32(&Vts[row][c4]),
                       g_Vt + (size_t)(kv * HD + row) * SQ + kb * 64 + c4);
        }
        CP_COMMIT();
        int haveK = kb < kbmax;
        if (haveK) {
#pragma unroll
            for (int j = 0; j < 8; j++) {
                int id = j * 256 + tid;
                int row = id >> 5, c4 = (id & 31) << 2;
                cp_async16(smem_u32(&Ks[(cur ^ 1) * 64 + row][c4]),
                           g_K + (size_t)((kb + 1) * 64 + row) * KVD + kv * HD + c4);
            }
            CP_COMMIT();
        }

        // ---- S = Q @ K^T : 128x64, warp n-tile 16 ----
        float sacc[4][2][4] = {};
#pragma unroll
        for (int ks = 0; ks < 16; ks++) {
            uint32_t a[4][4], b[2][2];
#pragma unroll
            for (int i = 0; i < 4; i++) {
                a[i][0] = __float_as_uint(Qs[wm + i * 16 + g][ks * 8 + t]);
                a[i][1] = __float_as_uint(Qs[wm + i * 16 + g + 8][ks * 8 + t]);
                a[i][2] = __float_as_uint(Qs[wm + i * 16 + g][ks * 8 + t + 4]);
                a[i][3] = __float_as_uint(Qs[wm + i * 16 + g + 8][ks * 8 + t + 4]);
            }
#pragma unroll
            for (int j = 0; j < 2; j++) {
                b[j][0] = __float_as_uint(Ks[cur * 64 + wq * 16 + j * 8 + g][ks * 8 + t]);
                b[j][1] = __float_as_uint(Ks[cur * 64 + wq * 16 + j * 8 + g][ks * 8 + t + 4]);
            }
#pragma unroll
            for (int i = 0; i < 4; i++)
#pragma unroll
                for (int j = 0; j < 2; j++)
                    mma_tf32(sacc[i][j], a[i], b[j]);
        }

        // ---- causal mask on diagonal k-tiles ----
        if (kb >= 2 * qb) {
#pragma unroll
            for (int i = 0; i < 4; i++)
#pragma unroll
                for (int j = 0; j < 2; j++)
#pragma unroll
                    for (int e = 0; e < 4; e++) {
                        int grow = qb * 128 + wm + i * 16 + g + (e >> 1) * 8;
                        int gcol = kb * 64 + wq * 16 + j * 8 + 2 * t + (e & 1);
                        if (gcol > grow) sacc[i][j][e] = -1e30f;
                    }
        }

        // ---- online softmax ----
        float pm[4][2];
#pragma unroll
        for (int i = 0; i < 4; i++)
#pragma unroll
            for (int hf = 0; hf < 2; hf++) {
                float v = fmaxf(fmaxf(sacc[i][0][hf * 2], sacc[i][0][hf * 2 + 1]),
                                fmaxf(sacc[i][1][hf * 2], sacc[i][1][hf * 2 + 1]));
                v = fmaxf(v, __shfl_xor_sync(0xffffffffu, v, 1));
                v = fmaxf(v, __shfl_xor_sync(0xffffffffu, v, 2));
                pm[i][hf] = v;
            }
        if (t == 0) {
#pragma unroll
            for (int i = 0; i < 4; i++) {
                red[wq * 128 + wm + i * 16 + g]     = pm[i][0];
                red[wq * 128 + wm + i * 16 + g + 8] = pm[i][1];
            }
        }
        __syncthreads();
        float mnew[4][2], fac[4][2];
#pragma unroll
        for (int i = 0; i < 4; i++)
#pragma unroll
            for (int hf = 0; hf < 2; hf++) {
                int r = wm + i * 16 + g + hf * 8;
                float v = fmaxf(fmaxf(red[r], red[128 + r]),
                                fmaxf(red[256 + r], red[384 + r]));
                v = fmaxf(v, mrow[i][hf]);
                fac[i][hf] = __expf(mrow[i][hf] - v);
                mnew[i][hf] = v;
                mrow[i][hf] = v;
            }
        __syncthreads();   // before red reuse for sums

        float psum[4][2] = {};
#pragma unroll
        for (int i = 0; i < 4; i++)
#pragma unroll
            for (int hf = 0; hf < 2; hf++) {
                float m = mnew[i][hf];
                float p0 = __expf(sacc[i][0][hf * 2] - m);
                float p1 = __expf(sacc[i][0][hf * 2 + 1] - m);
                float p2 = __expf(sacc[i][1][hf * 2] - m);
                float p3 = __expf(sacc[i][1][hf * 2 + 1] - m);
                psum[i][hf] = (p0 + p1) + (p2 + p3);
                int r = wm + i * 16 + g + hf * 8;
                *(float2*)&Ps[r][wq * 16 + 2 * t]     = make_float2(rna_tf32(p0), rna_tf32(p1));
                *(float2*)&Ps[r][wq * 16 + 8 + 2 * t] = make_float2(rna_tf32(p2), rna_tf32(p3));
            }
#pragma unroll
        for (int i = 0; i < 4; i++)
#pragma unroll
            for (int hf = 0; hf < 2; hf++) {
                float v = psum[i][hf];
                v += __shfl_xor_sync(0xffffffffu, v, 1);
                v += __shfl_xor_sync(0xffffffffu, v, 2);
                psum[i][hf] = v;
            }
        if (t == 0) {
#pragma unroll
            for (int i = 0; i < 4; i++) {
                red[wq * 128 + wm + i * 16 + g]     = psum[i][0];
                red[wq * 128 + wm + i * 16 + g + 8] = psum[i][1];
            }
        }
        // wait V (K may still be in flight), then barrier covers Ps + red + Vts
        if (haveK) asm volatile("cp.async.wait_group 1;" ::: "memory");
        else       asm volatile("cp.async.wait_group 0;" ::: "memory");
        __syncthreads();

#pragma unroll
        for (int i = 0; i < 4; i++)
#pragma unroll
            for (int hf = 0; hf < 2; hf++) {
                int r = wm + i * 16 + g + hf * 8;
                float s = (red[r] + red[128 + r]) + (red[256 + r] + red[384 + r]);
                lrow_[i][hf] = lrow_[i][hf] * fac[i][hf] + s;
            }
        // rescale O
#pragma unroll
        for (int i = 0; i < 4; i++)
#pragma unroll
            for (int j = 0; j < 4; j++) {
                Oacc[i][j][0] *= fac[i][0]; Oacc[i][j][1] *= fac[i][0];
                Oacc[i][j][2] *= fac[i][1]; Oacc[i][j][3] *= fac[i][1];
            }

        // ---- O += P @ V : 128x128, k extent 64, warp n-tile 32 ----
        int wn = wq * 32;
#pragma unroll
        for (int ks = 0; ks < 8; ks++) {
            uint32_t a[4][4], b[4][2];
#pragma unroll
            for (int i = 0; i < 4; i++) {
                a[i][0] = __float_as_uint(Ps[wm + i * 16 + g][ks * 8 + t]);
                a[i][1] = __float_as_uint(Ps[wm + i * 16 + g + 8][ks * 8 + t]);
                a[i][2] = __float_as_uint(Ps[wm + i * 16 + g][ks * 8 + t + 4]);
                a[i][3] = __float_as_uint(Ps[wm + i * 16 + g + 8][ks * 8 + t + 4]);
            }
#pragma unroll
            for (int j = 0; j < 4; j++) {
                b[j][0] = __float_as_uint(Vts[wn + j * 8 + g][ks * 8 + t]);
                b[j][1] = __float_as_uint(Vts[wn + j * 8 + g][ks * 8 + t + 4]);
            }
#pragma unroll
            for (int i = 0; i < 4; i++)
#pragma unroll
                for (int j = 0; j < 4; j++)
                    mma_tf32(Oacc[i][j], a[i], b[j]);
        }
    }

    // ---- epilogue: O / l, round, store ----
    int wn = wq * 32;
#pragma unroll
    for (int i = 0; i < 4; i++) {
        float inv0 = 1.f / lrow_[i][0];
        float inv1 = 1.f / lrow_[i][1];
#pragma unroll
        for (int j = 0; j < 4; j++) {
            int r0 = qb * 128 + wm + i * 16 + g;
            int cc = h * HD + wn + j * 8 + 2 * t;
            *(float2*)(g_A + (size_t)r0 * HID + cc) =
                make_float2(rna_tf32(Oacc[i][j][0] * inv0), rna_tf32(Oacc[i][j][1] * inv0));
            *(float2*)(g_A + (size_t)(r0 + 8) * HID + cc) =
                make_float2(rna_tf32(Oacc[i][j][2] * inv1), rna_tf32(Oacc[i][j][3] * inv1));
        }
    }
}

// ---------------------------------------------------------------------------
// RoPE in-place on g_Q (1/sqrt(hd) folded in) and g_K; outputs tf32-rounded.
// ---------------------------------------------------------------------------
__global__ void rope_kernel(const int* __restrict__ pos) {
    __shared__ float cs[64], sn[64];
    int s = blockIdx.x;
    float p = (float)pos[s];
    if (threadIdx.x < 64) {
        int d = threadIdx.x;
        float freq = (float)pow(10000.0, -(double)d / 64.0);
        float ang = p * freq;
        sincosf(ang, &sn[d], &cs[d]);
    }
    __syncthreads();
    const float scale = 0.08838834764831845f;  // 1/sqrt(128)
    for (int item = threadIdx.x; item < (NH + NKV) * 64; item += blockDim.x) {
        int head = item >> 6;
        int d    = item & 63;
        float* base;
        if (head < NH) base = g_Q + (size_t)s * HID + head * HD;
        else           base = g_K + (size_t)s * KVD + (head - NH) * HD;
        float x1 = base[d], x2 = base[d + 64];
        float c = cs[d], si = sn[d];
        float o1 = x1 * c - x2 * si;
        float o2 = x2 * c + x1 * si;
        if (head < NH) { o1 *= scale; o2 *= scale; }
        base[d]      = rna_tf32(o1);
        base[d + 64] = rna_tf32(o2);
    }
}

// ---------------------------------------------------------------------------
// V transpose: g_Vt[kv*HD + d][s] = g_V[s][kv*HD + d]   (already tf32)
// ---------------------------------------------------------------------------
__global__ __launch_bounds__(256) void transpose_v_kernel() {
    __shared__ float tb[32][33];
    int s0 = blockIdx.x * 32, d0 = blockIdx.y * 32, kv = blockIdx.z;
    int tx = threadIdx.x, ty = threadIdx.y;   // (32, 8)
#pragma unroll
    for (int i = 0; i < 4; i++)
        tb[ty + i * 8][tx] = g_V[(size_t)(s0 + ty + i * 8) * KVD + kv * HD + d0 + tx];
    __syncthreads();
#pragma unroll
    for (int i = 0; i < 4; i++)
        g_Vt[(size_t)(kv * HD + d0 + ty + i * 8) * SQ + s0 + tx] = tb[tx][ty + i * 8];
}

// ---------------------------------------------------------------------------
extern "C" void kernel_launch(void* const* d_in, const int* in_sizes, int n_in,
                              void* d_out, int out_size) {
    (void)in_sizes; (void)n_in; (void)out_size;
    const float* X   = (const float*)d_in[0];
    const int*   pos = (const int*)d_in[1];
    const float* Wq  = (const float*)d_in[2];
    const float* Wk  = (const float*)d_in[3];
    const float* Wv  = (const float*)d_in[4];
    const float* Wo  = (const float*)d_in[5];
    float* out = (float*)d_out;

    float *Qd, *Kd, *Vd, *Ad, *Xc, *Wqc, *Wkc, *Wvc, *Woc;
    cudaGetSymbolAddress((void**)&Qd,  g_Q);
    cudaGetSymbolAddress((void**)&Kd,  g_K);
    cudaGetSymbolAddress((void**)&Vd,  g_V);
    cudaGetSymbolAddress((void**)&Ad,  g_A);
    cudaGetSymbolAddress((void**)&Xc,  g_Xc);
    cudaGetSymbolAddress((void**)&Wqc, g_Wqc);
    cudaGetSymbolAddress((void**)&Wkc, g_Wkc);
    cudaGetSymbolAddress((void**)&Wvc, g_Wvc);
    cudaGetSymbolAddress((void**)&Woc, g_Woc);

    cudaFuncSetAttribute(flash_mma, cudaFuncAttributeMaxDynamicSharedMemorySize, FL_SMEM);

    // Round all GEMM inputs fp32 -> tf32 (RN)
    {
        int n4;
        n4 = SQ * HID / 4;
        round_tf32_kernel<<<(n4 + 255) / 256, 256>>>((const float4*)X,  (float4*)Xc,  n4);
        n4 = HID * HID / 4;
        round_tf32_kernel<<<(n4 + 255) / 256, 256>>>((const float4*)Wq, (float4*)Wqc, n4);
        n4 = KVD * HID / 4;
        round_tf32_kernel<<<(n4 + 255) / 256, 256>>>((const float4*)Wk, (float4*)Wkc, n4);
        round_tf32_kernel<<<(n4 + 255) / 256, 256>>>((const float4*)Wv, (float4*)Wvc, n4);
        n4 = HID * HID / 4;
        round_tf32_kernel<<<(n4 + 255) / 256, 256>>>((const float4*)Wo, (float4*)Woc, n4);
    }

    dim3 gBig(HID / 128, SQ / 128);   // (32, 16)
    dim3 gKV (KVD / 128, SQ / 128);   // (8, 16)

    gemm_mma<<<gBig, 256>>>(Xc, Wqc, Qd, SQ, HID, HID, 0);
    gemm_mma<<<gKV,  256>>>(Xc, Wkc, Kd, SQ, KVD, HID, 0);
    gemm_mma<<<gKV,  256>>>(Xc, Wvc, Vd, SQ, KVD, HID, 1);   // V rounded for mma
    rope_kernel<<<SQ, 256>>>(pos);
    transpose_v_kernel<<<dim3(SQ / 32, HD / 32, NKV), dim3(32, 8)>>>();
    flash_mma<<<dim3(SQ / 128, NH), 256, FL_SMEM>>>();
    gemm_mma<<<gBig, 256>>>(Ad, Woc, out, SQ, HID, HID, 0);
}

// round 11
// speedup vs baseline: 5.6659x; 1.8260x over previous
#include <cuda_runtime.h>
#include <cuda_fp16.h>
#include <math.h>
#include <float.h>
#include <stdint.h>

#define SQ   2048
#define HID  4096
#define NH   32
#define NKV  8
#define HD   128
#define KVD  1024   // NKV * HD

// Scratch (allocation-free rule: __device__ globals)
__device__ float  g_Q[SQ * HID];        // 32 MB  proj out fp32
__device__ float  g_K[SQ * KVD];        // 8 MB
__device__ float  g_V[SQ * KVD];        // 8 MB
__device__ __half g_Qh[SQ * HID];       // 16 MB  post-RoPE, scaled, fp16
__device__ __half g_Kh[SQ * KVD];       // 4 MB   post-RoPE fp16
__device__ __half g_Vth[KVD * SQ];      // 4 MB   V^T [kv*HD+d][s] fp16
__device__ __half g_Ah[SQ * HID];       // 16 MB  attention out fp16
// fp16 copies of GEMM inputs
__device__ __half g_Xh[SQ * HID];       // 16 MB
__device__ __half g_Wqh[HID * HID];     // 32 MB
__device__ __half g_Wkh[KVD * HID];     // 8 MB
__device__ __half g_Wvh[KVD * HID];     // 8 MB
__device__ __half g_Woh[HID * HID];     // 32 MB

__device__ __forceinline__ uint32_t smem_u32(const void* p) {
    uint32_t a;
    asm("{ .reg .u64 t; cvta.to.shared.u64 t, %1; cvt.u32.u64 %0, t; }" : "=r"(a) : "l"(p));
    return a;
}
__device__ __forceinline__ void cp_async16(uint32_t dst, const void* src) {
    asm volatile("cp.async.cg.shared.global [%0], [%1], 16;" :: "r"(dst), "l"(src) : "memory");
}
#define CP_COMMIT() asm volatile("cp.async.commit_group;" ::: "memory")

__device__ __forceinline__ void mma_h(float* c, const uint32_t* a, const uint32_t* b) {
    asm volatile(
        "mma.sync.aligned.m16n8k16.row.col.f32.f16.f16.f32 "
        "{%0,%1,%2,%3}, {%4,%5,%6,%7}, {%8,%9}, {%0,%1,%2,%3};"
        : "+f"(c[0]), "+f"(c[1]), "+f"(c[2]), "+f"(c[3])
        : "r"(a[0]), "r"(a[1]), "r"(a[2]), "r"(a[3]), "r"(b[0]), "r"(b[1]));
}

// ---------------------------------------------------------------------------
// fp32 -> fp16 (RN) conversion
// ---------------------------------------------------------------------------
__global__ void f2h_kernel(const float4* __restrict__ in,
                           uint2* __restrict__ out, int n4) {
    int i = blockIdx.x * blockDim.x + threadIdx.x;
    if (i < n4) {
        float4 v = in[i];
        __half2 lo = __floats2half2_rn(v.x, v.y);
        __half2 hi = __floats2half2_rn(v.z, v.w);
        out[i] = make_uint2(*(uint32_t*)&lo, *(uint32_t*)&hi);
    }
}

// ---------------------------------------------------------------------------
// fp16 GEMM: C[M,N] = A[M,K] @ B[N,K]^T (row-major, K-contiguous halves).
// CTA 128x128, 8 warps (2x4), warp tile 64x32, K staged 32 halves,
// double-buffered cp.async. Stage stride 40 halves -> conflict-free frags.
// ---------------------------------------------------------------------------
__global__ __launch_bounds__(256) void gemm_h(const __half* __restrict__ A,
                                              const __half* __restrict__ B,
                                              float* __restrict__ C,
                                              int M, int N, int K) {
    __shared__ __half As[2][128][40];
    __shared__ __half Bs[2][128][40];
    int tid = threadIdx.x, lane = tid & 31, wid = tid >> 5;
    int wm = (wid >> 2) * 64;
    int wn = (wid & 3) * 32;
    int g = lane >> 2, t = lane & 3;
    int lrow = tid >> 1, lcol = (tid & 1) * 16;
    uint32_t sA[2], sB[2];
    sA[0] = smem_u32(&As[0][lrow][lcol]); sA[1] = smem_u32(&As[1][lrow][lcol]);
    sB[0] = smem_u32(&Bs[0][lrow][lcol]); sB[1] = smem_u32(&Bs[1][lrow][lcol]);
    float acc[4][4][4] = {};

    int m0 = blockIdx.y * 128, n0 = blockIdx.x * 128;
    const __half* Ag = A + (size_t)(m0 + lrow) * K + lcol;
    const __half* Bg = B + (size_t)(n0 + lrow) * K + lcol;
    int S = K >> 5;   // stages of 32 halves

#define GH_LOAD(st) do { \
        int _b = (st) & 1; \
        const __half* _a  = Ag + (st) * 32; \
        const __half* _bg = Bg + (st) * 32; \
        cp_async16(sA[_b], _a);  cp_async16(sA[_b] + 16, _a + 8); \
        cp_async16(sB[_b], _bg); cp_async16(sB[_b] + 16, _bg + 8); \
        CP_COMMIT(); \
    } while (0)

    GH_LOAD(0);
    GH_LOAD(1);

    for (int kt = 0; kt < S; kt++) {
        if (kt < S - 1) asm volatile("cp.async.wait_group 1;" ::: "memory");
        else            asm volatile("cp.async.wait_group 0;" ::: "memory");
        __syncthreads();
        int buf = kt & 1;
#pragma unroll
        for (int kk = 0; kk < 32; kk += 16) {
            uint32_t a[4][4], b[4][2];
#pragma unroll
            for (int i = 0; i < 4; i++) {
                a[i][0] = *(const uint32_t*)&As[buf][wm + i * 16 + g][kk + 2 * t];
                a[i][1] = *(const uint32_t*)&As[buf][wm + i * 16 + g + 8][kk + 2 * t];
                a[i][2] = *(const uint32_t*)&As[buf][wm + i * 16 + g][kk + 2 * t + 8];
                a[i][3] = *(const uint32_t*)&As[buf][wm + i * 16 + g + 8][kk + 2 * t + 8];
            }
#pragma unroll
            for (int j = 0; j < 4; j++) {
                b[j][0] = *(const uint32_t*)&Bs[buf][wn + j * 8 + g][kk + 2 * t];
                b[j][1] = *(const uint32_t*)&Bs[buf][wn + j * 8 + g][kk + 2 * t + 8];
            }
#pragma unroll
            for (int i = 0; i < 4; i++)
#pragma unroll
                for (int j = 0; j < 4; j++)
                    mma_h(acc[i][j], a[i], b[j]);
        }
        __syncthreads();
        if (kt + 2 < S) GH_LOAD(kt + 2);
    }
#undef GH_LOAD

#pragma unroll
    for (int i = 0; i < 4; i++) {
#pragma unroll
        for (int j = 0; j < 4; j++) {
            int r0 = m0 + wm + i * 16 + g;
            int cc = n0 + wn + j * 8 + t * 2;
            *(float2*)(C + (size_t)r0 * N + cc)       = make_float2(acc[i][j][0], acc[i][j][1]);
            *(float2*)(C + (size_t)(r0 + 8) * N + cc) = make_float2(acc[i][j][2], acc[i][j][3]);
        }
    }
}

// ---------------------------------------------------------------------------
// Fused flash attention (fp16 mma): per CTA one 128-row q-tile of one head.
// k-tile 64, online softmax in fp32, O accumulated in fp32 registers.
// Smem (halves): Qs[128][136] | Ks[2*64][136] | Vts[128][72] | Ps[128][72]
//                red[4*128] floats
// ---------------------------------------------------------------------------
#define QS_B   0
#define KS_B   (QS_B + 128 * 136 * 2)
#define VT_B   (KS_B + 128 * 136 * 2)
#define PS_B   (VT_B + 128 * 72 * 2)
#define RED_B  (PS_B + 128 * 72 * 2)
#define FL_SMEM (RED_B + 4 * 128 * 4)

__global__ __launch_bounds__(256) void flash_h() {
    extern __shared__ char smc[];
    __half (*Qs)[136]  = (__half(*)[136])(smc + QS_B);
    __half (*Ks)[136]  = (__half(*)[136])(smc + KS_B);   // [buf*64 + row]
    __half (*Vts)[72]  = (__half(*)[72])(smc + VT_B);    // [d][k]
    __half (*Ps)[72]   = (__half(*)[72])(smc + PS_B);    // [q][k]
    float* red         = (float*)(smc + RED_B);          // [wq*128 + row]

    int qb = 15 - (int)blockIdx.x;       // long CTAs first
    int h  = blockIdx.y;
    int tid = threadIdx.x, lane = tid & 31, wid = tid >> 5;
    int wm = (wid >> 2) * 64;            // 0 / 64
    int wq = wid & 3;                    // n-warp index
    int g = lane >> 2, t = lane & 3;
    int kv = h >> 2;

    // ---- prologue: load Q tile (128x128 halves) and K tile 0 (64x128) ----
#pragma unroll
    for (int j = 0; j < 8; j++) {
        int id = j * 256 + tid;
        int row = id >> 4, c8 = (id & 15) * 8;
        cp_async16(smem_u32(&Qs[row][c8]),
                   g_Qh + (size_t)(qb * 128 + row) * HID + h * HD + c8);
    }
    CP_COMMIT();
#pragma unroll
    for (int j = 0; j < 4; j++) {
        int id = j * 256 + tid;
        int row = id >> 4, c8 = (id & 15) * 8;
        cp_async16(smem_u32(&Ks[row][c8]),
                   g_Kh + (size_t)row * KVD + kv * HD + c8);
    }
    CP_COMMIT();
    asm volatile("cp.async.wait_group 0;" ::: "memory");
    __syncthreads();

    float Oacc[4][4][4] = {};
    float mrow[4][2], lsum[4][2];
#pragma unroll
    for (int i = 0; i < 4; i++) { mrow[i][0] = mrow[i][1] = -1e30f; lsum[i][0] = lsum[i][1] = 0.f; }

    int kbmax = 2 * qb + 1;
    for (int kb = 0; kb <= kbmax; kb++) {
        int cur = kb & 1;
        if (kb) {
            asm volatile("cp.async.wait_group 0;" ::: "memory");
            __syncthreads();
        }
        // issue V[kb] (own group), then K[kb+1] (own group)
#pragma unroll
        for (int j = 0; j < 4; j++) {
            int id = j * 256 + tid;
            int row = id >> 3, c8 = (id & 7) * 8;
            cp_async16(smem_u32(&Vts[row][c8]),
                       g_Vth + (size_t)(kv * HD + row) * SQ + kb * 64 + c8);
        }
        CP_COMMIT();
        int haveK = kb < kbmax;
        if (haveK) {
#pragma unroll
            for (int j = 0; j < 4; j++) {
                int id = j * 256 + tid;
                int row = id >> 4, c8 = (id & 15) * 8;
                cp_async16(smem_u32(&Ks[(cur ^ 1) * 64 + row][c8]),
                           g_Kh + (size_t)((kb + 1) * 64 + row) * KVD + kv * HD + c8);
            }
            CP_COMMIT();
        }

        // ---- S = Q @ K^T : 128x64, k=128 -> 8 k16 steps, warp n-tile 16 ----
        float sacc[4][2][4] = {};
#pragma unroll
        for (int ks = 0; ks < 8; ks++) {
            uint32_t a[4][4], b[2][2];
#pragma unroll
            for (int i = 0; i < 4; i++) {
                a[i][0] = *(const uint32_t*)&Qs[wm + i * 16 + g][ks * 16 + 2 * t];
                a[i][1] = *(const uint32_t*)&Qs[wm + i * 16 + g + 8][ks * 16 + 2 * t];
                a[i][2] = *(const uint32_t*)&Qs[wm + i * 16 + g][ks * 16 + 2 * t + 8];
                a[i][3] = *(const uint32_t*)&Qs[wm + i * 16 + g + 8][ks * 16 + 2 * t + 8];
            }
#pragma unroll
            for (int j = 0; j < 2; j++) {
                b[j][0] = *(const uint32_t*)&Ks[cur * 64 + wq * 16 + j * 8 + g][ks * 16 + 2 * t];
                b[j][1] = *(const uint32_t*)&Ks[cur * 64 + wq * 16 + j * 8 + g][ks * 16 + 2 * t + 8];
            }
#pragma unroll
            for (int i = 0; i < 4; i++)
#pragma unroll
                for (int j = 0; j < 2; j++)
                    mma_h(sacc[i][j], a[i], b[j]);
        }

        // ---- causal mask on diagonal k-tiles ----
        if (kb >= 2 * qb) {
#pragma unroll
            for (int i = 0; i < 4; i++)
#pragma unroll
                for (int j = 0; j < 2; j++)
#pragma unroll
                    for (int e = 0; e < 4; e++) {
                        int grow = qb * 128 + wm + i * 16 + g + (e >> 1) * 8;
                        int gcol = kb * 64 + wq * 16 + j * 8 + 2 * t + (e & 1);
                        if (gcol > grow) sacc[i][j][e] = -1e30f;
                    }
        }

        // ---- online softmax ----
        float pm[4][2];
#pragma unroll
        for (int i = 0; i < 4; i++)
#pragma unroll
            for (int hf = 0; hf < 2; hf++) {
                float v = fmaxf(fmaxf(sacc[i][0][hf * 2], sacc[i][0][hf * 2 + 1]),
                                fmaxf(sacc[i][1][hf * 2], sacc[i][1][hf * 2 + 1]));
                v = fmaxf(v, __shfl_xor_sync(0xffffffffu, v, 1));
                v = fmaxf(v, __shfl_xor_sync(0xffffffffu, v, 2));
                pm[i][hf] = v;
            }
        if (t == 0) {
#pragma unroll
            for (int i = 0; i < 4; i++) {
                red[wq * 128 + wm + i * 16 + g]     = pm[i][0];
                red[wq * 128 + wm + i * 16 + g + 8] = pm[i][1];
            }
        }
        __syncthreads();
        float mnew[4][2], fac[4][2];
#pragma unroll
        for (int i = 0; i < 4; i++)
#pragma unroll
            for (int hf = 0; hf < 2; hf++) {
                int r = wm + i * 16 + g + hf * 8;
                float v = fmaxf(fmaxf(red[r], red[128 + r]),
                                fmaxf(red[256 + r], red[384 + r]));
                v = fmaxf(v, mrow[i][hf]);
                fac[i][hf] = __expf(mrow[i][hf] - v);
                mnew[i][hf] = v;
                mrow[i][hf] = v;
            }
        __syncthreads();   // before red reuse for sums

        float psum[4][2] = {};
#pragma unroll
        for (int i = 0; i < 4; i++)
#pragma unroll
            for (int hf = 0; hf < 2; hf++) {
                float m = mnew[i][hf];
                float p0 = __expf(sacc[i][0][hf * 2] - m);
                float p1 = __expf(sacc[i][0][hf * 2 + 1] - m);
                float p2 = __expf(sacc[i][1][hf * 2] - m);
                float p3 = __expf(sacc[i][1][hf * 2 + 1] - m);
                psum[i][hf] = (p0 + p1) + (p2 + p3);
                int r = wm + i * 16 + g + hf * 8;
                *(__half2*)&Ps[r][wq * 16 + 2 * t]     = __floats2half2_rn(p0, p1);
                *(__half2*)&Ps[r][wq * 16 + 8 + 2 * t] = __floats2half2_rn(p2, p3);
            }
#pragma unroll
        for (int i = 0; i < 4; i++)
#pragma unroll
            for (int hf = 0; hf < 2; hf++) {
                float v = psum[i][hf];
                v += __shfl_xor_sync(0xffffffffu, v, 1);
                v += __shfl_xor_sync(0xffffffffu, v, 2);
                psum[i][hf] = v;
            }
        if (t == 0) {
#pragma unroll
            for (int i = 0; i < 4; i++) {
                red[wq * 128 + wm + i * 16 + g]     = psum[i][0];
                red[wq * 128 + wm + i * 16 + g + 8] = psum[i][1];
            }
        }
        // wait V (K may still be in flight); barrier covers Ps + red + Vts
        if (haveK) asm volatile("cp.async.wait_group 1;" ::: "memory");
        else       asm volatile("cp.async.wait_group 0;" ::: "memory");
        __syncthreads();

#pragma unroll
        for (int i = 0; i < 4; i++)
#pragma unroll
            for (int hf = 0; hf < 2; hf++) {
                int r = wm + i * 16 + g + hf * 8;
                float s = (red[r] + red[128 + r]) + (red[256 + r] + red[384 + r]);
                lsum[i][hf] = lsum[i][hf] * fac[i][hf] + s;
            }
        // rescale O
#pragma unroll
        for (int i = 0; i < 4; i++)
#pragma unroll
            for (int j = 0; j < 4; j++) {
                Oacc[i][j][0] *= fac[i][0]; Oacc[i][j][1] *= fac[i][0];
                Oacc[i][j][2] *= fac[i][1]; Oacc[i][j][3] *= fac[i][1];
            }

        // ---- O += P @ V : 128x128, k=64 -> 4 k16 steps, warp n-tile 32 ----
        int wn = wq * 32;
#pragma unroll
        for (int ks = 0; ks < 4; ks++) {
            uint32_t a[4][4], b[4][2];
#pragma unroll
            for (int i = 0; i < 4; i++) {
                a[i][0] = *(const uint32_t*)&Ps[wm + i * 16 + g][ks * 16 + 2 * t];
                a[i][1] = *(const uint32_t*)&Ps[wm + i * 16 + g + 8][ks * 16 + 2 * t];
                a[i][2] = *(const uint32_t*)&Ps[wm + i * 16 + g][ks * 16 + 2 * t + 8];
                a[i][3] = *(const uint32_t*)&Ps[wm + i * 16 + g + 8][ks * 16 + 2 * t + 8];
            }
#pragma unroll
            for (int j = 0; j < 4; j++) {
                b[j][0] = *(const uint32_t*)&Vts[wn + j * 8 + g][ks * 16 + 2 * t];
                b[j][1] = *(const uint32_t*)&Vts[wn + j * 8 + g][ks * 16 + 2 * t + 8];
            }
#pragma unroll
            for (int i = 0; i < 4; i++)
#pragma unroll
                for (int j = 0; j < 4; j++)
                    mma_h(Oacc[i][j], a[i], b[j]);
        }
    }

    // ---- epilogue: O / l, convert fp16, store ----
    int wn = wq * 32;
#pragma unroll
    for (int i = 0; i < 4; i++) {
        float inv0 = 1.f / lsum[i][0];
        float inv1 = 1.f / lsum[i][1];
#pragma unroll
        for (int j = 0; j < 4; j++) {
            int r0 = qb * 128 + wm + i * 16 + g;
            int cc = h * HD + wn + j * 8 + 2 * t;
            *(__half2*)(g_Ah + (size_t)r0 * HID + cc) =
                __floats2half2_rn(Oacc[i][j][0] * inv0, Oacc[i][j][1] * inv0);
            *(__half2*)(g_Ah + (size_t)(r0 + 8) * HID + cc) =
                __floats2half2_rn(Oacc[i][j][2] * inv1, Oacc[i][j][3] * inv1);
        }
    }
}

// ---------------------------------------------------------------------------
// RoPE: reads fp32 proj outputs g_Q/g_K, applies rotation (+1/sqrt(hd) on Q),
// writes fp16 g_Qh / g_Kh.
// ---------------------------------------------------------------------------
__global__ void rope_kernel(const int* __restrict__ pos) {
    __shared__ float cs[64], sn[64];
    int s = blockIdx.x;
    float p = (float)pos[s];
    if (threadIdx.x < 64) {
        int d = threadIdx.x;
        float freq = (float)pow(10000.0, -(double)d / 64.0);
        float ang = p * freq;
        sincosf(ang, &sn[d], &cs[d]);
    }
    __syncthreads();
    const float scale = 0.08838834764831845f;  // 1/sqrt(128)
    for (int item = threadIdx.x; item < (NH + NKV) * 64; item += blockDim.x) {
        int head = item >> 6;
        int d    = item & 63;
        const float* base;
        __half* dst;
        if (head < NH) {
            base = g_Q + (size_t)s * HID + head * HD;
            dst  = g_Qh + (size_t)s * HID + head * HD;
        } else {
            base = g_K + (size_t)s * KVD + (head - NH) * HD;
            dst  = g_Kh + (size_t)s * KVD + (head - NH) * HD;
        }
        float x1 = base[d], x2 = base[d + 64];
        float c = cs[d], si = sn[d];
        float o1 = x1 * c - x2 * si;
        float o2 = x2 * c + x1 * si;
        if (head < NH) { o1 *= scale; o2 *= scale; }
        dst[d]      = __float2half_rn(o1);
        dst[d + 64] = __float2half_rn(o2);
    }
}

// ---------------------------------------------------------------------------
// V transpose + fp16: g_Vth[kv*HD + d][s] = fp16(g_V[s][kv*HD + d])
// ---------------------------------------------------------------------------
__global__ __launch_bounds__(256) void transpose_v_kernel() {
    __shared__ float tb[32][33];
    int s0 = blockIdx.x * 32, d0 = blockIdx.y * 32, kv = blockIdx.z;
    int tx = threadIdx.x, ty = threadIdx.y;   // (32, 8)
#pragma unroll
    for (int i = 0; i < 4; i++)
        tb[ty + i * 8][tx] = g_V[(size_t)(s0 + ty + i * 8) * KVD + kv * HD + d0 + tx];
    __syncthreads();
#pragma unroll
    for (int i = 0; i < 4; i++)
        g_Vth[(size_t)(kv * HD + d0 + ty + i * 8) * SQ + s0 + tx] =
            __float2half_rn(tb[tx][ty + i * 8]);
}

// ---------------------------------------------------------------------------
extern "C" void kernel_launch(void* const* d_in, const int* in_sizes, int n_in,
                              void* d_out, int out_size) {
    (void)in_sizes; (void)n_in; (void)out_size;
    const float* X   = (const float*)d_in[0];
    const int*   pos = (const int*)d_in[1];
    const float* Wq  = (const float*)d_in[2];
    const float* Wk  = (const float*)d_in[3];
    const float* Wv  = (const float*)d_in[4];
    const float* Wo  = (const float*)d_in[5];
    float* out = (float*)d_out;

    float *Qd, *Kd, *Vd;
    __half *Xh, *Wqh, *Wkh, *Wvh, *Woh, *Ah;
    cudaGetSymbolAddress((void**)&Qd,  g_Q);
    cudaGetSymbolAddress((void**)&Kd,  g_K);
    cudaGetSymbolAddress((void**)&Vd,  g_V);
    cudaGetSymbolAddress((void**)&Xh,  g_Xh);
    cudaGetSymbolAddress((void**)&Wqh, g_Wqh);
    cudaGetSymbolAddress((void**)&Wkh, g_Wkh);
    cudaGetSymbolAddress((void**)&Wvh, g_Wvh);
    cudaGetSymbolAddress((void**)&Woh, g_Woh);
    cudaGetSymbolAddress((void**)&Ah,  g_Ah);

    cudaFuncSetAttribute(flash_h, cudaFuncAttributeMaxDynamicSharedMemorySize, FL_SMEM);

    // Convert all GEMM inputs fp32 -> fp16 (RN)
    {
        int n4;
        n4 = SQ * HID / 4;
        f2h_kernel<<<(n4 + 255) / 256, 256>>>((const float4*)X,  (uint2*)Xh,  n4);
        n4 = HID * HID / 4;
        f2h_kernel<<<(n4 + 255) / 256, 256>>>((const float4*)Wq, (uint2*)Wqh, n4);
        n4 = KVD * HID / 4;
        f2h_kernel<<<(n4 + 255) / 256, 256>>>((const float4*)Wk, (uint2*)Wkh, n4);
        f2h_kernel<<<(n4 + 255) / 256, 256>>>((const float4*)Wv, (uint2*)Wvh, n4);
        n4 = HID * HID / 4;
        f2h_kernel<<<(n4 + 255) / 256, 256>>>((const float4*)Wo, (uint2*)Woh, n4);
    }

    dim3 gBig(HID / 128, SQ / 128);   // (32, 16)
    dim3 gKV (KVD / 128, SQ / 128);   // (8, 16)

    gemm_h<<<gBig, 256>>>(Xh, Wqh, Qd, SQ, HID, HID);
    gemm_h<<<gKV,  256>>>(Xh, Wkh, Kd, SQ, KVD, HID);
    gemm_h<<<gKV,  256>>>(Xh, Wvh, Vd, SQ, KVD, HID);
    rope_kernel<<<SQ, 256>>>(pos);
    transpose_v_kernel<<<dim3(SQ / 32, HD / 32, NKV), dim3(32, 8)>>>();
    flash_h<<<dim3(SQ / 128, NH), 256, FL_SMEM>>>();
    gemm_h<<<gBig, 256>>>(Ah, Woh, out, SQ, HID, HID);
}